// round 1
// baseline (speedup 1.0000x reference)
#include <cuda_runtime.h>
#include <cstddef>

#define B_ 2
#define T_ 4096
#define C_ 768
#define H_ 12
#define D_ 64
#define M_ (B_*T_)          // 8192 rows
#define N_QKV (3*C_)        // 2304
#define INV_SCALE 0.125f    // 1/sqrt(64)

// Scratch (allocation-free requirement -> __device__ globals)
__device__ float g_qkv[(size_t)M_ * N_QKV];   // [B*T, 3C]
__device__ float g_attn[(size_t)M_ * C_];     // [B*T, C]

// ---------------------------------------------------------------------------
// Tiled SGEMM with bias: C[M,N] = A[M,K] @ B[K,N] + bias[N]
// BM=BN=128, BK=8, 256 threads, each thread computes 8x8 (two 4-wide N chunks)
// Requires M%128==0, N%128==0, K%8==0 (true for all our shapes).
// ---------------------------------------------------------------------------
__global__ void __launch_bounds__(256)
sgemm_bias_kernel(const float* __restrict__ A, const float* __restrict__ B,
                  const float* __restrict__ bias, float* __restrict__ C,
                  int M, int N, int K)
{
    __shared__ float As[8][128];
    __shared__ float Bs[8][128];

    const int bx = blockIdx.x;           // N tile
    const int by = blockIdx.y;           // M tile
    const int tid = threadIdx.x;
    const int tx = tid & 15;             // 0..15 -> N
    const int ty = tid >> 4;             // 0..15 -> M

    float acc[8][8];
    #pragma unroll
    for (int i = 0; i < 8; i++)
        #pragma unroll
        for (int j = 0; j < 8; j++) acc[i][j] = 0.f;

    // Per-thread load coordinates
    const int a_row = tid >> 1;              // 0..127
    const int a_col = (tid & 1) * 4;         // 0 or 4
    const int b_row = tid >> 5;              // 0..7
    const int b_col = (tid & 31) * 4;        // 0..124

    const float* Aptr = A + (size_t)(by * 128 + a_row) * K + a_col;
    const float* Bptr = B + (size_t)b_row * N + bx * 128 + b_col;

    for (int k0 = 0; k0 < K; k0 += 8) {
        // Load A tile (128x8), transpose into As[k][m]
        float4 av = *reinterpret_cast<const float4*>(Aptr + k0);
        As[a_col + 0][a_row] = av.x;
        As[a_col + 1][a_row] = av.y;
        As[a_col + 2][a_row] = av.z;
        As[a_col + 3][a_row] = av.w;
        // Load B tile (8x128)
        float4 bv = *reinterpret_cast<const float4*>(Bptr + (size_t)k0 * N);
        *reinterpret_cast<float4*>(&Bs[b_row][b_col]) = bv;
        __syncthreads();

        #pragma unroll
        for (int kk = 0; kk < 8; kk++) {
            float a[8], b[8];
            #pragma unroll
            for (int i = 0; i < 8; i++) a[i] = As[kk][ty * 8 + i];
            // Two 4-wide chunks at tx*4 and 64+tx*4 (better bank behavior)
            #pragma unroll
            for (int j = 0; j < 4; j++) b[j]     = Bs[kk][tx * 4 + j];
            #pragma unroll
            for (int j = 0; j < 4; j++) b[4 + j] = Bs[kk][64 + tx * 4 + j];
            #pragma unroll
            for (int i = 0; i < 8; i++)
                #pragma unroll
                for (int j = 0; j < 8; j++)
                    acc[i][j] += a[i] * b[j];
        }
        __syncthreads();
    }

    // Epilogue: bias add + store (two float4 per row)
    const int col0 = bx * 128 + tx * 4;
    const int col1 = bx * 128 + 64 + tx * 4;
    float4 bia0 = *reinterpret_cast<const float4*>(bias + col0);
    float4 bia1 = *reinterpret_cast<const float4*>(bias + col1);
    #pragma unroll
    for (int i = 0; i < 8; i++) {
        const int row = by * 128 + ty * 8 + i;
        float4 o0, o1;
        o0.x = acc[i][0] + bia0.x; o0.y = acc[i][1] + bia0.y;
        o0.z = acc[i][2] + bia0.z; o0.w = acc[i][3] + bia0.w;
        o1.x = acc[i][4] + bia1.x; o1.y = acc[i][5] + bia1.y;
        o1.z = acc[i][6] + bia1.z; o1.w = acc[i][7] + bia1.w;
        *reinterpret_cast<float4*>(C + (size_t)row * N + col0) = o0;
        *reinterpret_cast<float4*>(C + (size_t)row * N + col1) = o1;
    }
}

// ---------------------------------------------------------------------------
// Flash-attention (causal), fp32, online softmax.
// grid = (T/128, B*H), block = 128 threads, thread t owns query row qtile*128+t.
// Q row + O accumulator in registers; K/V tiles (32 x 64) staged in smem.
// ---------------------------------------------------------------------------
__global__ void __launch_bounds__(128)
attn_kernel(const float* __restrict__ qkv, float* __restrict__ out)
{
    const int bh    = blockIdx.y;
    const int b     = bh / H_;
    const int h     = bh % H_;
    const int qtile = blockIdx.x;
    const int t     = threadIdx.x;
    const int qi    = qtile * 128 + t;

    __shared__ float Ks[32][D_];
    __shared__ float Vs[32][D_];

    // Load + pre-scale Q row into registers (16 x float4 = 64 floats)
    float4 Q[16];
    {
        const float* qp = qkv + (size_t)(b * T_ + qi) * N_QKV + h * D_;
        #pragma unroll
        for (int i = 0; i < 16; i++) {
            float4 v = reinterpret_cast<const float4*>(qp)[i];
            v.x *= INV_SCALE; v.y *= INV_SCALE; v.z *= INV_SCALE; v.w *= INV_SCALE;
            Q[i] = v;
        }
    }
    float4 O[16];
    #pragma unroll
    for (int i = 0; i < 16; i++) O[i] = make_float4(0.f, 0.f, 0.f, 0.f);
    float m = -1e30f, l = 0.f;

    const int ntiles = qtile * 4 + 4;   // ceil((qtile*128+128)/32): last needed KV tile
    for (int kt = 0; kt < ntiles; kt++) {
        const int kbase = kt * 32;
        __syncthreads();
        // Cooperative load of K,V tile: 32 rows x 16 float4 each
        #pragma unroll
        for (int it = 0; it < 4; it++) {
            const int idx = t + it * 128;      // 0..511
            const int row = idx >> 4;
            const int c4  = idx & 15;
            const size_t base = (size_t)(b * T_ + kbase + row) * N_QKV + h * D_ + c4 * 4;
            reinterpret_cast<float4*>(Ks[row])[c4] = *reinterpret_cast<const float4*>(qkv + base + C_);
            reinterpret_cast<float4*>(Vs[row])[c4] = *reinterpret_cast<const float4*>(qkv + base + 2 * C_);
        }
        __syncthreads();

        // S = Q . K^T (already scaled), causal mask
        float S[32];
        #pragma unroll 4
        for (int j = 0; j < 32; j++) {
            const float4* K4 = reinterpret_cast<const float4*>(Ks[j]);
            float s = 0.f;
            #pragma unroll
            for (int d = 0; d < 16; d++) {
                float4 kv = K4[d];
                s += Q[d].x * kv.x + Q[d].y * kv.y + Q[d].z * kv.z + Q[d].w * kv.w;
            }
            S[j] = (kbase + j <= qi) ? s : -1e30f;
        }

        // Online softmax update
        float mt = m;
        #pragma unroll
        for (int j = 0; j < 32; j++) mt = fmaxf(mt, S[j]);
        const float scale = __expf(m - mt);
        float lsum = 0.f;
        #pragma unroll
        for (int j = 0; j < 32; j++) { S[j] = __expf(S[j] - mt); lsum += S[j]; }
        l = l * scale + lsum;
        m = mt;

        #pragma unroll
        for (int i = 0; i < 16; i++) {
            O[i].x *= scale; O[i].y *= scale; O[i].z *= scale; O[i].w *= scale;
        }
        // O += P @ V
        #pragma unroll 4
        for (int j = 0; j < 32; j++) {
            const float4* V4 = reinterpret_cast<const float4*>(Vs[j]);
            const float p = S[j];
            #pragma unroll
            for (int d = 0; d < 16; d++) {
                float4 vv = V4[d];
                O[d].x += p * vv.x; O[d].y += p * vv.y;
                O[d].z += p * vv.z; O[d].w += p * vv.w;
            }
        }
    }

    const float inv_l = 1.f / l;
    float* op = out + (size_t)(b * T_ + qi) * C_ + h * D_;
    #pragma unroll
    for (int i = 0; i < 16; i++) {
        float4 v = O[i];
        v.x *= inv_l; v.y *= inv_l; v.z *= inv_l; v.w *= inv_l;
        reinterpret_cast<float4*>(op)[i] = v;
    }
}

// ---------------------------------------------------------------------------
// Launch: QKV GEMM -> attention -> output GEMM
// Inputs (metadata order): x[B,T,C], Wqkv[C,3C], bqkv[3C], Wout[C,C], bout[C]
// ---------------------------------------------------------------------------
extern "C" void kernel_launch(void* const* d_in, const int* in_sizes, int n_in,
                              void* d_out, int out_size)
{
    const float* x    = (const float*)d_in[0];
    const float* Wqkv = (const float*)d_in[1];
    const float* bqkv = (const float*)d_in[2];
    const float* Wout = (const float*)d_in[3];
    const float* bout = (const float*)d_in[4];
    float* out = (float*)d_out;

    float* qkv;  cudaGetSymbolAddress((void**)&qkv,  g_qkv);
    float* attn; cudaGetSymbolAddress((void**)&attn, g_attn);

    // 1) QKV projection: [8192,768] @ [768,2304] + bias
    {
        dim3 grid(N_QKV / 128, M_ / 128);
        sgemm_bias_kernel<<<grid, 256>>>(x, Wqkv, bqkv, qkv, M_, N_QKV, C_);
    }
    // 2) Causal attention
    {
        dim3 grid(T_ / 128, B_ * H_);
        attn_kernel<<<grid, 128>>>(qkv, attn);
    }
    // 3) Output projection: [8192,768] @ [768,768] + bias
    {
        dim3 grid(C_ / 128, M_ / 128);
        sgemm_bias_kernel<<<grid, 256>>>(attn, Wout, bout, out, M_, C_, C_);
    }
}

// round 3
// speedup vs baseline: 5.6448x; 5.6448x over previous
#include <cuda_runtime.h>
#include <cuda_fp16.h>
#include <cstdint>
#include <cstddef>

#define B_ 2
#define T_ 4096
#define C_ 768
#define H_ 12
#define D_ 64
#define M_ (B_*T_)          // 8192
#define N_QKV (3*C_)        // 2304
// softmax scale folded with log2(e) so we can use ex2
#define QSCALE (0.125f * 1.4426950408889634f)

// Scratch (allocation-free requirement -> __device__ globals)
__device__ float g_qkv[(size_t)M_ * N_QKV];   // [B*T, 3C]
__device__ float g_attn[(size_t)M_ * C_];     // [B*T, C]

// ---------------------------------------------------------------------------
// Helpers
// ---------------------------------------------------------------------------
__device__ __forceinline__ float to_tf32(float x) {
    uint32_t u;
    asm("cvt.rna.tf32.f32 %0, %1;" : "=r"(u) : "f"(x));
    return __uint_as_float(u);
}

__device__ __forceinline__ void mma_tf32(float* c, const uint32_t* a,
                                         uint32_t b0, uint32_t b1) {
    asm volatile(
        "mma.sync.aligned.m16n8k8.row.col.f32.tf32.tf32.f32 "
        "{%0,%1,%2,%3},{%4,%5,%6,%7},{%8,%9},{%0,%1,%2,%3};"
        : "+f"(c[0]), "+f"(c[1]), "+f"(c[2]), "+f"(c[3])
        : "r"(a[0]), "r"(a[1]), "r"(a[2]), "r"(a[3]), "r"(b0), "r"(b1));
}

__device__ __forceinline__ void mma_f16(float* c, const uint32_t* a,
                                        uint32_t b0, uint32_t b1) {
    asm volatile(
        "mma.sync.aligned.m16n8k16.row.col.f32.f16.f16.f32 "
        "{%0,%1,%2,%3},{%4,%5,%6,%7},{%8,%9},{%0,%1,%2,%3};"
        : "+f"(c[0]), "+f"(c[1]), "+f"(c[2]), "+f"(c[3])
        : "r"(a[0]), "r"(a[1]), "r"(a[2]), "r"(a[3]), "r"(b0), "r"(b1));
}

__device__ __forceinline__ uint32_t pack_h2(float lo, float hi) {
    __half2 h = __floats2half2_rn(lo, hi);
    return *reinterpret_cast<uint32_t*>(&h);
}

__device__ __forceinline__ float fast_exp2(float x) {
    float r;
    asm("ex2.approx.ftz.f32 %0, %1;" : "=f"(r) : "f"(x));
    return r;
}

// ---------------------------------------------------------------------------
// tf32 tensor-core GEMM with bias: C[M,N] = A[M,K] @ B[K,N] + bias[N]
// BM=BN=128, BK=16, 256 threads (8 warps), warp tile 64x32 (m16n8k8).
// Requires M%128==0, N%128==0, K%16==0.
// ---------------------------------------------------------------------------
__global__ void __launch_bounds__(256)
gemm_tf32_kernel(const float* __restrict__ A, const float* __restrict__ B,
                 const float* __restrict__ bias, float* __restrict__ C,
                 int M, int N, int K)
{
    __shared__ float As[128][20];   // [m][k], pitch 20 -> conflict-free frags
    __shared__ float Bs[16][136];   // [k][n], pitch 136 (==8 mod 32) -> conflict-free

    const int tid = threadIdx.x;
    const int wid = tid >> 5;
    const int lane = tid & 31;
    const int g = lane >> 2;       // 0..7
    const int t4 = lane & 3;       // 0..3
    const int wm = wid >> 2;       // 0..1 -> m offset wm*64
    const int wn = wid & 3;        // 0..3 -> n offset wn*32
    const int bx = blockIdx.x, by = blockIdx.y;

    float acc[4][4][4];
    #pragma unroll
    for (int mt = 0; mt < 4; mt++)
        #pragma unroll
        for (int nt = 0; nt < 4; nt++)
            #pragma unroll
            for (int i = 0; i < 4; i++) acc[mt][nt][i] = 0.f;

    const int ar = tid >> 2;            // 0..63 (rows ar, ar+64)
    const int ac = (tid & 3) * 4;
    const int br = tid >> 5;            // 0..7 (rows br, br+8)
    const int bc = (lane) * 4;

    for (int k0 = 0; k0 < K; k0 += 16) {
        // A tile 128x16 (convert to tf32 at store)
        #pragma unroll
        for (int h = 0; h < 2; h++) {
            const int row = ar + h * 64;
            float4 v = *reinterpret_cast<const float4*>(
                A + (size_t)(by * 128 + row) * K + k0 + ac);
            As[row][ac + 0] = to_tf32(v.x);
            As[row][ac + 1] = to_tf32(v.y);
            As[row][ac + 2] = to_tf32(v.z);
            As[row][ac + 3] = to_tf32(v.w);
        }
        // B tile 16x128
        #pragma unroll
        for (int h = 0; h < 2; h++) {
            const int row = br + h * 8;
            float4 v = *reinterpret_cast<const float4*>(
                B + (size_t)(k0 + row) * N + bx * 128 + bc);
            Bs[row][bc + 0] = to_tf32(v.x);
            Bs[row][bc + 1] = to_tf32(v.y);
            Bs[row][bc + 2] = to_tf32(v.z);
            Bs[row][bc + 3] = to_tf32(v.w);
        }
        __syncthreads();

        #pragma unroll
        for (int kk = 0; kk < 16; kk += 8) {
            uint32_t afr[4][4], bfr[4][2];
            #pragma unroll
            for (int mt = 0; mt < 4; mt++) {
                const int row = wm * 64 + mt * 16;
                afr[mt][0] = __float_as_uint(As[row + g][kk + t4]);
                afr[mt][1] = __float_as_uint(As[row + g + 8][kk + t4]);
                afr[mt][2] = __float_as_uint(As[row + g][kk + t4 + 4]);
                afr[mt][3] = __float_as_uint(As[row + g + 8][kk + t4 + 4]);
            }
            #pragma unroll
            for (int nt = 0; nt < 4; nt++) {
                const int col = wn * 32 + nt * 8 + g;
                bfr[nt][0] = __float_as_uint(Bs[kk + t4][col]);
                bfr[nt][1] = __float_as_uint(Bs[kk + t4 + 4][col]);
            }
            #pragma unroll
            for (int mt = 0; mt < 4; mt++)
                #pragma unroll
                for (int nt = 0; nt < 4; nt++)
                    mma_tf32(acc[mt][nt], afr[mt], bfr[nt][0], bfr[nt][1]);
        }
        __syncthreads();
    }

    // Epilogue: bias + store (float2 pairs, C-layout)
    #pragma unroll
    for (int nt = 0; nt < 4; nt++) {
        const int col = bx * 128 + wn * 32 + nt * 8 + 2 * t4;
        const float b0 = bias[col], b1 = bias[col + 1];
        #pragma unroll
        for (int mt = 0; mt < 4; mt++) {
            const int row = by * 128 + wm * 64 + mt * 16 + g;
            float2 o0 = make_float2(acc[mt][nt][0] + b0, acc[mt][nt][1] + b1);
            float2 o1 = make_float2(acc[mt][nt][2] + b0, acc[mt][nt][3] + b1);
            *reinterpret_cast<float2*>(C + (size_t)row * N + col) = o0;
            *reinterpret_cast<float2*>(C + (size_t)(row + 8) * N + col) = o1;
        }
    }
}

// ---------------------------------------------------------------------------
// Flash attention (causal), tensor cores.
// grid = (T/64, B*H), 128 threads (4 warps). Br=Bc=64, D=64.
// Warp w owns query rows [w*16, w*16+16). QK^T in tf32 mma, softmax in regs,
// P->fp16 (C-layout == A-layout trick), PV in fp16 mma, fp32 accum.
// ---------------------------------------------------------------------------
__global__ void __launch_bounds__(128)
attn_mma_kernel(const float* __restrict__ qkv, float* __restrict__ out)
{
    __shared__ float Ks[64][68];    // Q first, then K tiles (tf32-rounded)
    __shared__ __half Vs[64][72];   // transposed: [d][k]

    const int bh = blockIdx.y;
    const int b = bh / H_;
    const int h = bh % H_;
    const int qtile = blockIdx.x;
    const int tid = threadIdx.x;
    const int w = tid >> 5;
    const int lane = tid & 31;
    const int g = lane >> 2;
    const int t4 = lane & 3;

    // ---- load Q tile (pre-scaled, tf32-rounded) ----
    #pragma unroll
    for (int i = 0; i < 8; i++) {
        const int idx = tid + i * 128;      // 0..1023
        const int r = idx >> 4;
        const int c4 = (idx & 15) * 4;
        float4 v = *reinterpret_cast<const float4*>(
            qkv + (size_t)(b * T_ + qtile * 64 + r) * N_QKV + h * D_ + c4);
        Ks[r][c4 + 0] = to_tf32(v.x * QSCALE);
        Ks[r][c4 + 1] = to_tf32(v.y * QSCALE);
        Ks[r][c4 + 2] = to_tf32(v.z * QSCALE);
        Ks[r][c4 + 3] = to_tf32(v.w * QSCALE);
    }
    __syncthreads();

    // ---- Q fragments to registers: 8 k-chunks x 4 regs ----
    uint32_t Qa[8][4];
    #pragma unroll
    for (int kc = 0; kc < 8; kc++) {
        const int row = w * 16;
        Qa[kc][0] = __float_as_uint(Ks[row + g][kc * 8 + t4]);
        Qa[kc][1] = __float_as_uint(Ks[row + g + 8][kc * 8 + t4]);
        Qa[kc][2] = __float_as_uint(Ks[row + g][kc * 8 + t4 + 4]);
        Qa[kc][3] = __float_as_uint(Ks[row + g + 8][kc * 8 + t4 + 4]);
    }

    float o[8][4];
    #pragma unroll
    for (int nt = 0; nt < 8; nt++)
        #pragma unroll
        for (int i = 0; i < 4; i++) o[nt][i] = 0.f;
    float m0 = -1e30f, m1 = -1e30f, l0 = 0.f, l1 = 0.f;

    for (int kt = 0; kt <= qtile; kt++) {
        __syncthreads();    // previous Ks/Vs consumers done
        // ---- load K (tf32) and V (fp16 transposed) tiles ----
        #pragma unroll
        for (int i = 0; i < 8; i++) {
            const int idx = tid + i * 128;
            const int r = idx >> 4;
            const int c4 = (idx & 15) * 4;
            const size_t base =
                (size_t)(b * T_ + kt * 64 + r) * N_QKV + h * D_ + c4;
            float4 kv = *reinterpret_cast<const float4*>(qkv + base + C_);
            Ks[r][c4 + 0] = to_tf32(kv.x);
            Ks[r][c4 + 1] = to_tf32(kv.y);
            Ks[r][c4 + 2] = to_tf32(kv.z);
            Ks[r][c4 + 3] = to_tf32(kv.w);
            float4 vv = *reinterpret_cast<const float4*>(qkv + base + 2 * C_);
            Vs[c4 + 0][r] = __float2half(vv.x);
            Vs[c4 + 1][r] = __float2half(vv.y);
            Vs[c4 + 2][r] = __float2half(vv.z);
            Vs[c4 + 3][r] = __float2half(vv.w);
        }
        __syncthreads();

        // ---- S = Q @ K^T (16x64 per warp) ----
        float s[8][4];
        #pragma unroll
        for (int nt = 0; nt < 8; nt++)
            #pragma unroll
            for (int i = 0; i < 4; i++) s[nt][i] = 0.f;
        #pragma unroll
        for (int kc = 0; kc < 8; kc++) {
            #pragma unroll
            for (int nt = 0; nt < 8; nt++) {
                uint32_t b0 = __float_as_uint(Ks[nt * 8 + g][kc * 8 + t4]);
                uint32_t b1 = __float_as_uint(Ks[nt * 8 + g][kc * 8 + t4 + 4]);
                mma_tf32(s[nt], Qa[kc], b0, b1);
            }
        }

        // ---- causal mask on diagonal tile ----
        if (kt == qtile) {
            const int q0 = w * 16 + g;      // local row in [0,64)
            const int q1 = q0 + 8;
            #pragma unroll
            for (int nt = 0; nt < 8; nt++) {
                const int c0 = nt * 8 + 2 * t4;
                if (c0 > q0)     s[nt][0] = -1e30f;
                if (c0 + 1 > q0) s[nt][1] = -1e30f;
                if (c0 > q1)     s[nt][2] = -1e30f;
                if (c0 + 1 > q1) s[nt][3] = -1e30f;
            }
        }

        // ---- online softmax (base-2) ----
        float mx0 = -1e30f, mx1 = -1e30f;
        #pragma unroll
        for (int nt = 0; nt < 8; nt++) {
            mx0 = fmaxf(mx0, fmaxf(s[nt][0], s[nt][1]));
            mx1 = fmaxf(mx1, fmaxf(s[nt][2], s[nt][3]));
        }
        mx0 = fmaxf(mx0, __shfl_xor_sync(0xffffffff, mx0, 1));
        mx0 = fmaxf(mx0, __shfl_xor_sync(0xffffffff, mx0, 2));
        mx1 = fmaxf(mx1, __shfl_xor_sync(0xffffffff, mx1, 1));
        mx1 = fmaxf(mx1, __shfl_xor_sync(0xffffffff, mx1, 2));
        const float nm0 = fmaxf(m0, mx0), nm1 = fmaxf(m1, mx1);
        const float sc0 = fast_exp2(m0 - nm0), sc1 = fast_exp2(m1 - nm1);
        m0 = nm0; m1 = nm1;

        float rs0 = 0.f, rs1 = 0.f;
        #pragma unroll
        for (int nt = 0; nt < 8; nt++) {
            s[nt][0] = fast_exp2(s[nt][0] - m0); rs0 += s[nt][0];
            s[nt][1] = fast_exp2(s[nt][1] - m0); rs0 += s[nt][1];
            s[nt][2] = fast_exp2(s[nt][2] - m1); rs1 += s[nt][2];
            s[nt][3] = fast_exp2(s[nt][3] - m1); rs1 += s[nt][3];
        }
        rs0 += __shfl_xor_sync(0xffffffff, rs0, 1);
        rs0 += __shfl_xor_sync(0xffffffff, rs0, 2);
        rs1 += __shfl_xor_sync(0xffffffff, rs1, 1);
        rs1 += __shfl_xor_sync(0xffffffff, rs1, 2);
        l0 = l0 * sc0 + rs0;
        l1 = l1 * sc1 + rs1;

        #pragma unroll
        for (int nt = 0; nt < 8; nt++) {
            o[nt][0] *= sc0; o[nt][1] *= sc0;
            o[nt][2] *= sc1; o[nt][3] *= sc1;
        }

        // ---- O += P @ V  (fp16 mma; C-layout -> A-layout pack) ----
        #pragma unroll
        for (int kc = 0; kc < 4; kc++) {
            uint32_t pa[4];
            pa[0] = pack_h2(s[2 * kc][0], s[2 * kc][1]);
            pa[1] = pack_h2(s[2 * kc][2], s[2 * kc][3]);
            pa[2] = pack_h2(s[2 * kc + 1][0], s[2 * kc + 1][1]);
            pa[3] = pack_h2(s[2 * kc + 1][2], s[2 * kc + 1][3]);
            #pragma unroll
            for (int nt = 0; nt < 8; nt++) {
                uint32_t b0 = *reinterpret_cast<const uint32_t*>(
                    &Vs[nt * 8 + g][kc * 16 + 2 * t4]);
                uint32_t b1 = *reinterpret_cast<const uint32_t*>(
                    &Vs[nt * 8 + g][kc * 16 + 2 * t4 + 8]);
                mma_f16(o[nt], pa, b0, b1);
            }
        }
    }

    // ---- normalize + store ----
    const float inv0 = 1.f / l0, inv1 = 1.f / l1;
    const size_t row0 = (size_t)(b * T_ + qtile * 64 + w * 16 + g);
    const size_t row1 = row0 + 8;
    #pragma unroll
    for (int nt = 0; nt < 8; nt++) {
        const int col = h * D_ + nt * 8 + 2 * t4;
        float2 v0 = make_float2(o[nt][0] * inv0, o[nt][1] * inv0);
        float2 v1 = make_float2(o[nt][2] * inv1, o[nt][3] * inv1);
        *reinterpret_cast<float2*>(out + row0 * C_ + col) = v0;
        *reinterpret_cast<float2*>(out + row1 * C_ + col) = v1;
    }
}

// ---------------------------------------------------------------------------
// Launch
// ---------------------------------------------------------------------------
extern "C" void kernel_launch(void* const* d_in, const int* in_sizes, int n_in,
                              void* d_out, int out_size)
{
    const float* x    = (const float*)d_in[0];
    const float* Wqkv = (const float*)d_in[1];
    const float* bqkv = (const float*)d_in[2];
    const float* Wout = (const float*)d_in[3];
    const float* bout = (const float*)d_in[4];
    float* out = (float*)d_out;

    float* qkv;  cudaGetSymbolAddress((void**)&qkv,  g_qkv);
    float* attn; cudaGetSymbolAddress((void**)&attn, g_attn);

    // 1) QKV projection: [8192,768] @ [768,2304] + bias
    {
        dim3 grid(N_QKV / 128, M_ / 128);
        gemm_tf32_kernel<<<grid, 256>>>(x, Wqkv, bqkv, qkv, M_, N_QKV, C_);
    }
    // 2) Causal attention (flash, tensor cores)
    {
        dim3 grid(T_ / 64, B_ * H_);
        attn_mma_kernel<<<grid, 128>>>(qkv, attn);
    }
    // 3) Output projection: [8192,768] @ [768,768] + bias
    {
        dim3 grid(C_ / 128, M_ / 128);
        gemm_tf32_kernel<<<grid, 256>>>(attn, Wout, bout, out, M_, C_, C_);
    }
}